// round 6
// baseline (speedup 1.0000x reference)
#include <cuda_runtime.h>

#define B_TOTAL  8192
#define T_STEPS  512
#define HID      128
#define BM       32      // batch rows per CTA (16 row-pairs)
#define NPAIR    16
#define NKQ      33      // k-quads: 128 h + 2 x + 2 pad = 132 k's
#define PITCHF   264     // floats per pair-row: 256 h (pair-interleaved) + 4 x/pad
#define NTHREADS 128     // 4 warps; 2 CTAs/SM for phase-decoupled overlap
#define ALPHA_C  0.2f
#define BETA_C   0.7f

typedef unsigned long long u64;

__device__ __forceinline__ u64 pack2(float lo, float hi) {
    u64 r; asm("mov.b64 %0, {%1, %2};" : "=l"(r) : "f"(lo), "f"(hi)); return r;
}
__device__ __forceinline__ void unpack2(u64 v, float& lo, float& hi) {
    asm("mov.b64 {%0, %1}, %2;" : "=f"(lo), "=f"(hi) : "l"(v));
}
// c += a*b (packed f32x2 -> SASS FFMA2)
__device__ __forceinline__ void fma2(u64& c, u64 a, u64 b) {
    asm("fma.rn.f32x2 %0, %1, %2, %0;" : "+l"(c) : "l"(a), "l"(b));
}
// c = c*b + h (packed)
__device__ __forceinline__ void fma2s(u64& c, u64 b, u64 h) {
    asm("fma.rn.f32x2 %0, %0, %1, %2;" : "+l"(c) : "l"(b), "l"(h));
}

__device__ __forceinline__ float tanh_fast(float x) {
    float e = __expf(2.0f * x);
    return 1.0f - __fdividef(2.0f, e + 1.0f);
}

extern __shared__ float smem[];

__global__ __launch_bounds__(NTHREADS, 2)
void rnn_kernel(const float* __restrict__ input,   // (B, T, 2)
                const float* __restrict__ W_rec,   // (130, 128)
                const float* __restrict__ b_rec,   // (128)
                const float* __restrict__ W_out,   // (128, 1)
                const float* __restrict__ b_out,   // (1)
                float* __restrict__ out)           // (B)
{
    float* sW  = smem;                        // [132][128] dense, k-major
    float* sA0 = smem + 132 * HID;            // 16 pair-rows x 264 floats
    float* sA1 = sA0 + NPAIR * PITCHF;

    const int tid = threadIdx.x;
    const int cg  = tid & 31;   // lane: 4 n-columns
    const int rg  = tid >> 5;   // warp: 4 row-pairs (8 rows)
    const int n0  = cg * 4;
    const int rgP = rg * 4;
    const int rowBase = rg * 8;
    const int bBase   = blockIdx.x * BM;

    // Reordered W: k<128 -> W_rec[k+2] (hidden), 128/129 -> x, >=130 -> 0
    for (int idx = tid; idx < 132 * HID; idx += NTHREADS) {
        int k = idx >> 7;
        int n = idx & 127;
        float v;
        if      (k < 128) v = W_rec[(k + 2) * HID + n];
        else if (k < 130) v = W_rec[(k - 128) * HID + n];
        else              v = 0.0f;
        sW[idx] = v;
    }
    // Zero both state buffers (h_{-1}=0, pads=0)
    for (int idx = tid; idx < 2 * NPAIR * PITCHF; idx += NTHREADS) sA0[idx] = 0.0f;

    float wout[4];
    u64   bias2[4];
    #pragma unroll
    for (int n = 0; n < 4; n++) {
        float b = b_rec[n0 + n];
        bias2[n] = pack2(b, b);
        wout[n]  = W_out[n0 + n];
    }
    const float bout = b_out[0];
    const u64 beta2 = pack2(BETA_C, BETA_C);

    const int  myLocalRow = rowBase + cg;      // lanes 0..7 own a batch row
    const int  myP   = myLocalRow >> 1;
    const int  myPar = myLocalRow & 1;
    const long long rowOff = (long long)(bBase + myLocalRow) * T_STEPS * 2;

    float  racc = 0.0f, prevx0 = 0.0f;
    float2 xcur = make_float2(0.0f, 0.0f);
    if (cg < 8) {
        xcur = *(const float2*)(input + rowOff);       // x_0 -> buffer 0
        sA0[myP * PITCHF + 256 + myPar] = xcur.x;
        sA0[myP * PITCHF + 258 + myPar] = xcur.y;
    }
    __syncthreads();

    u64 hacc2[4][4];   // beta-weighted sum of h, packed {row 2j, row 2j+1}
    #pragma unroll
    for (int j = 0; j < 4; j++)
        #pragma unroll
        for (int nn = 0; nn < 4; nn++) hacc2[j][nn] = 0ULL;

    float* cur = sA0;
    float* nxt = sA1;

    for (int t = 0; t < T_STEPS; ++t) {
        // Prefetch x_{t+1}
        float2 xnext = make_float2(0.0f, 0.0f);
        if (cg < 8 && t + 1 < T_STEPS)
            xnext = *(const float2*)(input + rowOff + (long long)(t + 1) * 2);

        u64 acc2[4][4];
        #pragma unroll
        for (int j = 0; j < 4; j++) {
            acc2[j][0] = bias2[0]; acc2[j][1] = bias2[1];
            acc2[j][2] = bias2[2]; acc2[j][3] = bias2[3];
        }

        // GEMM: 33 kq x (8 broadcast a-LDS.128 + 4 w-LDS.128 + 16 packs + 64 FFMA2)
        #pragma unroll 3
        for (int kq = 0; kq < NKQ; ++kq) {
            u64 a2[4][4];
            #pragma unroll
            for (int j = 0; j < 4; j++) {
                const float* base = cur + (rgP + j) * PITCHF + 8 * kq;
                ulonglong2 lo = *(const ulonglong2*)(base);
                ulonglong2 hi = *(const ulonglong2*)(base + 4);
                a2[j][0] = lo.x; a2[j][1] = lo.y;
                a2[j][2] = hi.x; a2[j][3] = hi.y;
            }
            #pragma unroll
            for (int kk = 0; kk < 4; kk++) {
                float4 w = *(const float4*)(sW + (4 * kq + kk) * HID + n0);
                u64 wd[4];
                wd[0] = pack2(w.x, w.x);
                wd[1] = pack2(w.y, w.y);
                wd[2] = pack2(w.z, w.z);
                wd[3] = pack2(w.w, w.w);
                #pragma unroll
                for (int j = 0; j < 4; j++) {
                    fma2(acc2[j][0], a2[j][kk], wd[0]);
                    fma2(acc2[j][1], a2[j][kk], wd[1]);
                    fma2(acc2[j][2], a2[j][kk], wd[2]);
                    fma2(acc2[j][3], a2[j][kk], wd[3]);
                }
            }
        }

        // tanh -> packed h; store; beta-accumulate
        #pragma unroll
        for (int j = 0; j < 4; j++) {
            u64 h2[4];
            #pragma unroll
            for (int nn = 0; nn < 4; nn++) {
                float lo, hi;
                unpack2(acc2[j][nn], lo, hi);
                h2[nn] = pack2(tanh_fast(lo), tanh_fast(hi));
            }
            float* dst = nxt + (rgP + j) * PITCHF + 8 * cg;
            ulonglong2 s0; s0.x = h2[0]; s0.y = h2[1];
            ulonglong2 s1; s1.x = h2[2]; s1.y = h2[3];
            *(ulonglong2*)(dst)     = s0;
            *(ulonglong2*)(dst + 4) = s1;
            fma2s(hacc2[j][0], beta2, h2[0]);
            fma2s(hacc2[j][1], beta2, h2[1]);
            fma2s(hacc2[j][2], beta2, h2[2]);
            fma2s(hacc2[j][3], beta2, h2[3]);
        }

        // resid-term recursion (prevx0 is 0 on lanes >= 8 -> harmless)
        racc = racc * BETA_C + prevx0 * prevx0;
        prevx0 = xcur.x;
        if (cg < 8) {
            nxt[myP * PITCHF + 256 + myPar] = xnext.x;
            nxt[myP * PITCHF + 258 + myPar] = xnext.y;
            xcur = xnext;
        }
        __syncthreads();
        float* tmp = cur; cur = nxt; nxt = tmp;
    }

    // One-time reduction: omega-part = hacc . W_out, butterfly over 32 lanes
    float ol[4], oh[4];
    #pragma unroll
    for (int j = 0; j < 4; j++) {
        u64 p2 = 0ULL;
        u64 w2;
        w2 = pack2(wout[0], wout[0]); fma2(p2, hacc2[j][0], w2);
        w2 = pack2(wout[1], wout[1]); fma2(p2, hacc2[j][1], w2);
        w2 = pack2(wout[2], wout[2]); fma2(p2, hacc2[j][2], w2);
        w2 = pack2(wout[3], wout[3]); fma2(p2, hacc2[j][3], w2);
        float lo, hi; unpack2(p2, lo, hi);
        #pragma unroll
        for (int s = 16; s >= 1; s >>= 1) {
            lo += __shfl_xor_sync(0xffffffffu, lo, s);
            hi += __shfl_xor_sync(0xffffffffu, hi, s);
        }
        ol[j] = lo; oh[j] = hi;
    }

    if (cg < 8) {
        const int jj = cg >> 1;
        float om = (jj == 0) ? (myPar ? oh[0] : ol[0])
                 : (jj == 1) ? (myPar ? oh[1] : ol[1])
                 : (jj == 2) ? (myPar ? oh[2] : ol[2])
                 :             (myPar ? oh[3] : ol[3]);
        // beta^512 underflows float -> geometric sum = 1/(1-beta)
        const float geo = 1.0f / (1.0f - BETA_C);
        out[bBase + myLocalRow] = racc * ALPHA_C + om + bout * geo;
    }
}

extern "C" void kernel_launch(void* const* d_in, const int* in_sizes, int n_in,
                              void* d_out, int out_size) {
    const float* input = (const float*)d_in[0];
    const float* W_rec = (const float*)d_in[1];
    const float* b_rec = (const float*)d_in[2];
    const float* W_out = (const float*)d_in[3];
    const float* b_out = (const float*)d_in[4];
    float* out = (float*)d_out;

    const size_t smem_bytes = (size_t)(132 * HID + 2 * NPAIR * PITCHF) * sizeof(float); // 101376
    cudaFuncSetAttribute(rnn_kernel, cudaFuncAttributeMaxDynamicSharedMemorySize,
                         (int)smem_bytes);

    rnn_kernel<<<B_TOTAL / BM, NTHREADS, smem_bytes>>>(input, W_rec, b_rec,
                                                       W_out, b_out, out);
    (void)in_sizes; (void)n_in; (void)out_size;
}

// round 8
// speedup vs baseline: 1.1447x; 1.1447x over previous
#include <cuda_runtime.h>

#define B_TOTAL  8192
#define T_STEPS  512
#define HID      128
#define BM       64      // batch rows per CTA (32 row-pairs)
#define NPAIR    32
#define NKQ      32      // K = 128 exactly (x/bias folded into acc init)
#define PITCHF   256     // floats per pair-row (128 k's pair-interleaved)
#define NTHREADS 256
#define ALPHA_C  0.2f
#define BETA_C   0.7f

typedef unsigned long long u64;

__device__ __forceinline__ u64 pack2(float lo, float hi) {
    u64 r; asm("mov.b64 %0, {%1, %2};" : "=l"(r) : "f"(lo), "f"(hi)); return r;
}
__device__ __forceinline__ void unpack2(u64 v, float& lo, float& hi) {
    asm("mov.b64 {%0, %1}, %2;" : "=f"(lo), "=f"(hi) : "l"(v));
}
// c += a*b (packed f32x2 -> SASS FFMA2)
__device__ __forceinline__ void fma2(u64& c, u64 a, u64 b) {
    asm("fma.rn.f32x2 %0, %1, %2, %0;" : "+l"(c) : "l"(a), "l"(b));
}
// c = c*b + h (packed)
__device__ __forceinline__ void fma2s(u64& c, u64 b, u64 h) {
    asm("fma.rn.f32x2 %0, %0, %1, %2;" : "+l"(c) : "l"(b), "l"(h));
}
// HW tanh (MUFU.TANH): 1 MUFU op, abs err ~5e-4
__device__ __forceinline__ float tanh_hw(float x) {
    float y; asm("tanh.approx.f32 %0, %1;" : "=f"(y) : "f"(x)); return y;
}

extern __shared__ float smem[];

__global__ __launch_bounds__(NTHREADS, 1)
void rnn_kernel(const float* __restrict__ input,   // (B, T, 2)
                const float* __restrict__ W_rec,   // (130, 128)
                const float* __restrict__ b_rec,   // (128)
                const float* __restrict__ W_out,   // (128, 1)
                const float* __restrict__ b_out,   // (1)
                float* __restrict__ out)           // (B)
{
    // layout: sW[128*128] | sA0[32*256] | sA1[32*256] | sX0[128] | sX1[128] | sRed[64]
    float* sW  = smem;
    float* sA0 = sW  + 128 * HID;
    float* sA1 = sA0 + NPAIR * PITCHF;
    float* sX0 = sA1 + NPAIR * PITCHF;
    float* sX1 = sX0 + 4 * NPAIR;
    float* sRed = sX1 + 4 * NPAIR;

    const int tid = threadIdx.x;
    const int cg  = tid & 31;   // lane: 4 n-columns
    const int rg  = tid >> 5;   // warp: 4 row-pairs (8 rows)
    const int n0  = cg * 4;
    const int rgP = rg * 4;
    const int rowBase = rg * 8;
    const int bBase   = blockIdx.x * BM;

    // W hidden part only: sW[k][n] = W_rec[k+2][n]
    for (int idx = tid; idx < 128 * HID; idx += NTHREADS)
        sW[idx] = W_rec[(idx >> 7) * HID + 256 + (idx & 127)];
    // Zero h buffer 0 (h_{-1} = 0)
    for (int idx = tid; idx < NPAIR * PITCHF; idx += NTHREADS) sA0[idx] = 0.0f;

    float wout[4];
    u64   bias2[4], wx0d[4], wx1d[4];
    #pragma unroll
    for (int n = 0; n < 4; n++) {
        float b = b_rec[n0 + n];
        bias2[n] = pack2(b, b);
        float w0 = W_rec[n0 + n];          // W_rec row 0 (x0)
        float w1 = W_rec[HID + n0 + n];    // W_rec row 1 (x1)
        wx0d[n] = pack2(w0, w0);
        wx1d[n] = pack2(w1, w1);
        wout[n] = W_out[n0 + n];
    }
    const float bout = b_out[0];
    const u64 beta2 = pack2(BETA_C, BETA_C);

    // x loader: threads 0..63, one batch row each
    const long long rowOff = (long long)(bBase + (tid & 63)) * T_STEPS * 2;
    float  racc = 0.0f, prevx0 = 0.0f;
    float2 xcur = make_float2(0.0f, 0.0f);
    if (tid < BM) {
        xcur = *(const float2*)(input + rowOff);       // x_0 -> buffer 0
        const int p = tid >> 1, par = tid & 1;
        sX0[p * 4 + par]     = xcur.x;
        sX0[p * 4 + 2 + par] = xcur.y;
    }
    __syncthreads();

    u64 hacc2[4][4];   // beta-weighted sum of h, packed {row 2j, row 2j+1}
    #pragma unroll
    for (int j = 0; j < 4; j++)
        #pragma unroll
        for (int nn = 0; nn < 4; nn++) hacc2[j][nn] = 0ULL;

    float* curA = sA0; float* nxtA = sA1;
    float* curX = sX0; float* nxtX = sX1;

    for (int t = 0; t < T_STEPS; ++t) {
        // Prefetch x_{t+1}
        float2 xnext = make_float2(0.0f, 0.0f);
        if (tid < BM && t + 1 < T_STEPS)
            xnext = *(const float2*)(input + rowOff + (long long)(t + 1) * 2);

        // acc init: bias + x0*Wx0 + x1*Wx1 (x via broadcast LDS.128 per pair)
        u64 acc2[4][4];
        #pragma unroll
        for (int j = 0; j < 4; j++) {
            float4 xp = *(const float4*)(curX + (rgP + j) * 4); // {x0e,x0o,x1e,x1o}
            u64 x0p = pack2(xp.x, xp.y);
            u64 x1p = pack2(xp.z, xp.w);
            #pragma unroll
            for (int nn = 0; nn < 4; nn++) {
                u64 a = bias2[nn];
                fma2(a, x0p, wx0d[nn]);
                fma2(a, x1p, wx1d[nn]);
                acc2[j][nn] = a;
            }
        }

        // GEMM: 32 kq x (8 broadcast a-LDS.128 + 4 w-LDS.128 + 16 packs + 64 FFMA2)
        #pragma unroll 4
        for (int kq = 0; kq < NKQ; ++kq) {
            u64 a2[4][4];
            #pragma unroll
            for (int j = 0; j < 4; j++) {
                const float* base = curA + (rgP + j) * PITCHF + 8 * kq;
                ulonglong2 lo = *(const ulonglong2*)(base);
                ulonglong2 hi = *(const ulonglong2*)(base + 4);
                a2[j][0] = lo.x; a2[j][1] = lo.y;
                a2[j][2] = hi.x; a2[j][3] = hi.y;
            }
            #pragma unroll
            for (int kk = 0; kk < 4; kk++) {
                float4 w = *(const float4*)(sW + (4 * kq + kk) * HID + n0);
                u64 wd[4];
                wd[0] = pack2(w.x, w.x);
                wd[1] = pack2(w.y, w.y);
                wd[2] = pack2(w.z, w.z);
                wd[3] = pack2(w.w, w.w);
                #pragma unroll
                for (int j = 0; j < 4; j++) {
                    fma2(acc2[j][0], a2[j][kk], wd[0]);
                    fma2(acc2[j][1], a2[j][kk], wd[1]);
                    fma2(acc2[j][2], a2[j][kk], wd[2]);
                    fma2(acc2[j][3], a2[j][kk], wd[3]);
                }
            }
        }

        // tanh (HW) -> packed h; store; beta-accumulate
        #pragma unroll
        for (int j = 0; j < 4; j++) {
            u64 h2[4];
            #pragma unroll
            for (int nn = 0; nn < 4; nn++) {
                float lo, hi;
                unpack2(acc2[j][nn], lo, hi);
                h2[nn] = pack2(tanh_hw(lo), tanh_hw(hi));
            }
            float* dst = nxtA + (rgP + j) * PITCHF + 8 * cg;
            ulonglong2 s0; s0.x = h2[0]; s0.y = h2[1];
            ulonglong2 s1; s1.x = h2[2]; s1.y = h2[3];
            *(ulonglong2*)(dst)     = s0;
            *(ulonglong2*)(dst + 4) = s1;
            fma2s(hacc2[j][0], beta2, h2[0]);
            fma2s(hacc2[j][1], beta2, h2[1]);
            fma2s(hacc2[j][2], beta2, h2[2]);
            fma2s(hacc2[j][3], beta2, h2[3]);
        }

        // x_{t+1} into next buffer + resid recursion (loader threads)
        if (tid < BM) {
            const int p = tid >> 1, par = tid & 1;
            nxtX[p * 4 + par]     = xnext.x;
            nxtX[p * 4 + 2 + par] = xnext.y;
            racc = racc * BETA_C + prevx0 * prevx0;
            prevx0 = xcur.x;
            xcur = xnext;
        }
        __syncthreads();
        float* tA = curA; curA = nxtA; nxtA = tA;
        float* tX = curX; curX = nxtX; nxtX = tX;
    }

    // loader threads publish racc
    if (tid < BM) sRed[tid] = racc;
    __syncthreads();

    // One-time reduction: omega-part = hacc . W_out, butterfly over 32 lanes
    float ol[4], oh[4];
    #pragma unroll
    for (int j = 0; j < 4; j++) {
        u64 p2 = 0ULL;
        u64 w2;
        w2 = pack2(wout[0], wout[0]); fma2(p2, hacc2[j][0], w2);
        w2 = pack2(wout[1], wout[1]); fma2(p2, hacc2[j][1], w2);
        w2 = pack2(wout[2], wout[2]); fma2(p2, hacc2[j][2], w2);
        w2 = pack2(wout[3], wout[3]); fma2(p2, hacc2[j][3], w2);
        float lo, hi; unpack2(p2, lo, hi);
        #pragma unroll
        for (int s = 16; s >= 1; s >>= 1) {
            lo += __shfl_xor_sync(0xffffffffu, lo, s);
            hi += __shfl_xor_sync(0xffffffffu, hi, s);
        }
        ol[j] = lo; oh[j] = hi;
    }

    if (cg < 8) {
        const int myLocalRow = rowBase + cg;
        const int myPar = myLocalRow & 1;
        const int jj = cg >> 1;
        float om = (jj == 0) ? (myPar ? oh[0] : ol[0])
                 : (jj == 1) ? (myPar ? oh[1] : ol[1])
                 : (jj == 2) ? (myPar ? oh[2] : ol[2])
                 :             (myPar ? oh[3] : ol[3]);
        // beta^512 underflows float -> geometric sum = 1/(1-beta)
        const float geo = 1.0f / (1.0f - BETA_C);
        out[bBase + myLocalRow] = sRed[myLocalRow] * ALPHA_C + om + bout * geo;
    }
}

extern "C" void kernel_launch(void* const* d_in, const int* in_sizes, int n_in,
                              void* d_out, int out_size) {
    const float* input = (const float*)d_in[0];
    const float* W_rec = (const float*)d_in[1];
    const float* b_rec = (const float*)d_in[2];
    const float* W_out = (const float*)d_in[3];
    const float* b_out = (const float*)d_in[4];
    float* out = (float*)d_out;

    const size_t smem_bytes =
        (size_t)(128 * HID + 2 * NPAIR * PITCHF + 8 * NPAIR + BM) * sizeof(float); // ~132 KB
    cudaFuncSetAttribute(rnn_kernel, cudaFuncAttributeMaxDynamicSharedMemorySize,
                         (int)smem_bytes);

    rnn_kernel<<<B_TOTAL / BM, NTHREADS, smem_bytes>>>(input, W_rec, b_rec,
                                                       W_out, b_out, out);
    (void)in_sizes; (void)n_in; (void)out_size;
}